// round 4
// baseline (speedup 1.0000x reference)
#include <cuda_runtime.h>
#include <cuda_bf16.h>

#define NPTS   8192
#define KNBR   64
#define CIN    64
#define H1DIM  64
#define H2DIM  128
#define ODIM   256
#define R2     0.015625f   // 0.125^2 exactly
#define CAP    192         // candidate cap (mean ~60 in-radius)

typedef unsigned long long ull;

// Scratch (device globals; no allocation allowed)
__device__ int    g_nbr[NPTS * KNBR];
__device__ float  g_G  [NPTS * CIN];        // x @ W1[:64] + b1
__device__ float  g_AGG[NPTS * H2DIM];      // max-aggregated h2
__device__ float2 g_W2d[H1DIM * H2DIM];     // W2 duplicated (w,w)
__device__ float2 g_Wgd[H2DIM * ODIM];      // Wg duplicated (w,w)

__device__ __forceinline__ void fma2(ull& d, ull a, ull b) {
    asm("fma.rn.f32x2 %0, %1, %2, %0;" : "+l"(d) : "l"(a), "l"(b));
}

// ---------------------------------------------------------------------------
// Prep: duplicate W2 / Wg entries into (w,w) float2 for packed f32x2 FMA.
// ---------------------------------------------------------------------------
__global__ void prep_kernel(const float* __restrict__ W2, const float* __restrict__ Wg)
{
    int t = blockIdx.x * 256 + threadIdx.x;
    if (t < H1DIM * H2DIM) {
        float w = W2[t];
        g_W2d[t] = make_float2(w, w);
    }
    int t2 = t - H1DIM * H2DIM;
    if (t2 >= 0 && t2 < H2DIM * ODIM) {
        float w = Wg[t2];
        g_Wgd[t2] = make_float2(w, w);
    }
}

// ---------------------------------------------------------------------------
// KNN: 8 target points per block, 256 threads share the j-sweep.
// Radius filter into shared candidate lists; exact (d2,idx) rank selection
// if count > K (matches jax top_k tie-breaking); pad with self.
// ---------------------------------------------------------------------------
__global__ void __launch_bounds__(256) knn_kernel(const float* __restrict__ pos, int n)
{
    __shared__ float cd2 [8][CAP];
    __shared__ int   cidx[8][CAP];
    __shared__ int   cnt[8];

    const int tid = threadIdx.x;
    const int i0  = blockIdx.x * 8;
    if (tid < 8) cnt[tid] = 0;
    __syncthreads();

    float qx[8], qy[8], qz[8], sqi[8];
    #pragma unroll
    for (int t = 0; t < 8; t++) {
        int i = i0 + t; if (i >= n) i = n - 1;
        qx[t] = pos[3 * i + 0];
        qy[t] = pos[3 * i + 1];
        qz[t] = pos[3 * i + 2];
        sqi[t] = qx[t] * qx[t] + qy[t] * qy[t] + qz[t] * qz[t];
    }

    for (int j = tid; j < n; j += 256) {
        const float px = pos[3 * j + 0];
        const float py = pos[3 * j + 1];
        const float pz = pos[3 * j + 2];
        const float sqj = px * px + py * py + pz * pz;
        #pragma unroll
        for (int t = 0; t < 8; t++) {
            const float dot = px * qx[t] + py * qy[t] + pz * qz[t];
            const float d2  = (sqi[t] + sqj) - 2.0f * dot;   // same formula as reference
            if (d2 <= R2) {
                int p = atomicAdd(&cnt[t], 1);
                if (p < CAP) { cd2[t][p] = d2; cidx[t][p] = j; }
            }
        }
    }
    __syncthreads();

    #pragma unroll
    for (int s = 0; s < 2; s++) {
        const int slot = tid + s * 256;     // 512 (target, lane) pairs
        const int t = slot >> 6;
        const int l = slot & 63;
        const int i = i0 + t;
        if (i >= n) continue;

        int M = cnt[t]; if (M > CAP) M = CAP;

        if (M <= KNBR) {
            g_nbr[i * KNBR + l] = (l < M) ? cidx[t][l] : i;   // pad with self
        } else {
            for (int m = l; m < M; m += 64) {
                const float dm = cd2[t][m];
                const int   im = cidx[t][m];
                int rank = 0;
                for (int q = 0; q < M; q++) {
                    const float dq = cd2[t][q];
                    rank += (dq < dm) || (dq == dm && cidx[t][q] < im);
                }
                if (rank < KNBR) g_nbr[i * KNBR + rank] = cidx[t][m];
            }
        }
    }
}

// ---------------------------------------------------------------------------
// G precompute: G = x @ W1[0:64,:] + b1   (per-source-point layer-1 part)
// ---------------------------------------------------------------------------
__global__ void __launch_bounds__(128) g_kernel(
    const float* __restrict__ x, const float* __restrict__ W1,
    const float* __restrict__ b1, int n)
{
    __shared__ __align__(16) float xs[8 * 64];
    const int tid = threadIdx.x;
    const int i0  = blockIdx.x * 8;

    for (int idx = tid; idx < 512; idx += 128) {
        int p = idx >> 6, d = idx & 63;
        xs[idx] = (i0 + p < n) ? x[(size_t)(i0 + p) * 64 + d] : 0.0f;
    }
    __syncthreads();

    const int p  = tid >> 4;
    const int c4 = (tid & 15) * 4;
    if (i0 + p >= n) return;

    float4 acc = *(const float4*)&b1[c4];
    const float* xr = &xs[p * 64];
    #pragma unroll 8
    for (int d = 0; d < 64; d++) {
        const float xv = xr[d];
        float4 w = *(const float4*)&W1[d * 64 + c4];
        acc.x = fmaf(xv, w.x, acc.x);
        acc.y = fmaf(xv, w.y, acc.y);
        acc.z = fmaf(xv, w.z, acc.z);
        acc.w = fmaf(xv, w.w, acc.w);
    }
    *(float4*)&g_G[(size_t)(i0 + p) * 64 + c4] = acc;
}

// ---------------------------------------------------------------------------
// Main edge kernel: one block per point, 128 threads, 6 blocks/SM.
// Phase A: h1[c][nk] = relu(G[j] + rel @ W1[64:67]) into shared [c][nk].
// Phase B: per-thread output channel c2; TWO passes of 32 neighbors with
//          16 packed f32x2 accumulators each (register diet -> occupancy).
// ---------------------------------------------------------------------------
__global__ void __launch_bounds__(128, 6) compute_kernel(
    const float* __restrict__ pos, const float* __restrict__ W1,
    const float* __restrict__ b2, int n)
{
    __shared__ __align__(16) float H1s[H1DIM * 68];   // [c][nk], stride 68
    __shared__ int   nbr_s[KNBR];
    __shared__ float relx[KNBR], rely[KNBR], relz[KNBR];

    const int i   = blockIdx.x;
    const int tid = threadIdx.x;
    if (i >= n) return;

    if (tid < KNBR) {
        const int j = g_nbr[i * KNBR + tid];
        nbr_s[tid] = j;
        relx[tid] = pos[3 * j + 0] - pos[3 * i + 0];
        rely[tid] = pos[3 * j + 1] - pos[3 * i + 1];
        relz[tid] = pos[3 * j + 2] - pos[3 * i + 2];
    }
    __syncthreads();

    // ---- Phase A ----
    {
        const int nk0 = tid & 7;
        const int c4  = (tid >> 3) * 4;
        const float4 wx = *(const float4*)&W1[64 * 64 + c4];
        const float4 wy = *(const float4*)&W1[65 * 64 + c4];
        const float4 wz = *(const float4*)&W1[66 * 64 + c4];
        #pragma unroll
        for (int it = 0; it < 8; it++) {
            const int nk = nk0 + it * 8;
            const int j  = nbr_s[nk];
            const float4 g4 = *(const float4*)&g_G[(size_t)j * 64 + c4];
            const float rx = relx[nk], ry = rely[nk], rz = relz[nk];
            float4 a;
            a.x = fmaf(rx, wx.x, fmaf(ry, wy.x, fmaf(rz, wz.x, g4.x)));
            a.y = fmaf(rx, wx.y, fmaf(ry, wy.y, fmaf(rz, wz.y, g4.y)));
            a.z = fmaf(rx, wx.z, fmaf(ry, wy.z, fmaf(rz, wz.z, g4.z)));
            a.w = fmaf(rx, wx.w, fmaf(ry, wy.w, fmaf(rz, wz.w, g4.w)));
            H1s[(c4 + 0) * 68 + nk] = fmaxf(a.x, 0.0f);
            H1s[(c4 + 1) * 68 + nk] = fmaxf(a.y, 0.0f);
            H1s[(c4 + 2) * 68 + nk] = fmaxf(a.z, 0.0f);
            H1s[(c4 + 3) * 68 + nk] = fmaxf(a.w, 0.0f);
        }
    }
    __syncthreads();

    // ---- Phase B: layer 2 + max-agg (packed f32x2, 2 passes of 32 nbrs) ----
    {
        const int c2 = tid;    // 0..127
        float mx = -1e30f;
        const ull* const w2p0 = reinterpret_cast<const ull*>(g_W2d) + c2;

        #pragma unroll
        for (int pass = 0; pass < 2; pass++) {
            ull acc[16];
            #pragma unroll
            for (int g = 0; g < 16; g++) acc[g] = 0ull;

            const ull*   wp = w2p0;
            const float* hr = &H1s[pass * 32];
            #pragma unroll 4
            for (int d = 0; d < H1DIM; d++) {
                const ull wd = *wp; wp += H2DIM;
                #pragma unroll
                for (int g = 0; g < 8; g++) {
                    const ulonglong2 hv = *reinterpret_cast<const ulonglong2*>(hr + 4 * g);
                    fma2(acc[2 * g + 0], hv.x, wd);
                    fma2(acc[2 * g + 1], hv.y, wd);
                }
                hr += 68;
            }
            #pragma unroll
            for (int g = 0; g < 16; g++) {
                const float lo = __uint_as_float((unsigned)(acc[g] & 0xffffffffu));
                const float hi = __uint_as_float((unsigned)(acc[g] >> 32));
                mx = fmaxf(mx, fmaxf(lo, hi));
            }
        }
        // relu(max_j(z_j) + b2) == max_j relu(z_j + b2) since max is monotone
        g_AGG[(size_t)i * H2DIM + c2] = fmaxf(mx + b2[c2], 0.0f);
    }
}

// ---------------------------------------------------------------------------
// Global layer GEMM: out = relu(AGG @ Wg + bg). 32-point tiles, 256 threads,
// packed f32x2 accumulation over rows, Wg duplicated pairs from g_Wgd.
// ---------------------------------------------------------------------------
__global__ void __launch_bounds__(256) gemm_kernel(
    const float* __restrict__ bg, float* __restrict__ out, int n)
{
    __shared__ __align__(16) float As[H2DIM * 36];   // [d][r], stride 36
    const int tid = threadIdx.x;
    const int i0  = blockIdx.x * 32;

    for (int idx = tid; idx < 32 * H2DIM; idx += 256) {
        const int r = idx >> 7, d = idx & 127;
        const int row = (i0 + r < n) ? (i0 + r) : (n - 1);
        As[d * 36 + r] = g_AGG[(size_t)row * H2DIM + d];
    }
    __syncthreads();

    const int c = tid;   // output channel 0..255
    ull acc[16];
    #pragma unroll
    for (int p = 0; p < 16; p++) acc[p] = 0ull;

    const ull* wp = reinterpret_cast<const ull*>(g_Wgd) + c;
    #pragma unroll 2
    for (int d = 0; d < H2DIM; d++) {
        const ull wd = *wp; wp += ODIM;
        const float* ar = &As[d * 36];
        #pragma unroll
        for (int p = 0; p < 8; p++) {
            const ulonglong2 av = *reinterpret_cast<const ulonglong2*>(ar + 4 * p);
            fma2(acc[2 * p + 0], av.x, wd);
            fma2(acc[2 * p + 1], av.y, wd);
        }
    }

    const float bc = bg[c];
    #pragma unroll
    for (int k = 0; k < 16; k++) {          // acc[k] -> rows (2k, 2k+1)
        const float lo = __uint_as_float((unsigned)(acc[k] & 0xffffffffu));
        const float hi = __uint_as_float((unsigned)(acc[k] >> 32));
        const int r0 = i0 + 2 * k, r1 = r0 + 1;
        if (r0 < n) out[(size_t)r0 * ODIM + c] = fmaxf(lo + bc, 0.0f);
        if (r1 < n) out[(size_t)r1 * ODIM + c] = fmaxf(hi + bc, 0.0f);
    }
}

// ---------------------------------------------------------------------------
extern "C" void kernel_launch(void* const* d_in, const int* in_sizes, int n_in,
                              void* d_out, int out_size)
{
    const float* x   = (const float*)d_in[0];
    const float* pos = (const float*)d_in[1];
    // d_in[2] = batch (all zeros, unused)
    const float* W1  = (const float*)d_in[3];
    const float* b1  = (const float*)d_in[4];
    const float* W2  = (const float*)d_in[5];
    const float* b2  = (const float*)d_in[6];
    const float* Wg  = (const float*)d_in[7];
    const float* bg  = (const float*)d_in[8];
    float* out = (float*)d_out;

    const int n = in_sizes[2];   // batch vector length == N

    prep_kernel<<<(H1DIM * H2DIM + H2DIM * ODIM + 255) / 256, 256>>>(W2, Wg);
    knn_kernel<<<(n + 7) / 8, 256>>>(pos, n);
    g_kernel<<<(n + 7) / 8, 128>>>(x, W1, b1, n);
    compute_kernel<<<n, 128>>>(pos, W1, b2, n);
    gemm_kernel<<<(n + 31) / 32, 256>>>(bg, out, n);
}

// round 5
// speedup vs baseline: 1.4014x; 1.4014x over previous
#include <cuda_runtime.h>
#include <cuda_bf16.h>

#define NPTS   8192
#define KNBR   64
#define CIN    64
#define H1DIM  64
#define H2DIM  128
#define ODIM   256
#define R2     0.015625f   // 0.125^2 exactly
#define CAP    192         // candidate cap (mean ~60 in-radius)

typedef unsigned long long ull;

// Scratch (device globals; no allocation allowed)
__device__ int    g_nbr[NPTS * KNBR];
__device__ float  g_G  [NPTS * CIN];        // x @ W1[:64] + b1
__device__ float  g_AGG[NPTS * H2DIM];      // max-aggregated h2
__device__ float2 g_W2d[H1DIM * H2DIM];     // W2 duplicated (w,w)
__device__ float2 g_Wgd[H2DIM * ODIM];      // Wg duplicated (w,w)

__device__ __forceinline__ void fma2(ull& d, ull a, ull b) {
    asm("fma.rn.f32x2 %0, %1, %2, %0;" : "+l"(d) : "l"(a), "l"(b));
}

// ---------------------------------------------------------------------------
// Prep: duplicate W2 / Wg entries into (w,w) float2 for packed f32x2 FMA.
// ---------------------------------------------------------------------------
__global__ void prep_kernel(const float* __restrict__ W2, const float* __restrict__ Wg)
{
    int t = blockIdx.x * 256 + threadIdx.x;
    if (t < H1DIM * H2DIM) {
        float w = W2[t];
        g_W2d[t] = make_float2(w, w);
    }
    int t2 = t - H1DIM * H2DIM;
    if (t2 >= 0 && t2 < H2DIM * ODIM) {
        float w = Wg[t2];
        g_Wgd[t2] = make_float2(w, w);
    }
}

// ---------------------------------------------------------------------------
// KNN: 4 target points per block, 256 threads share the j-sweep.
// Radius filter into shared candidate lists; exact (d2,idx) rank selection
// if count > K (matches jax top_k tie-breaking); pad with self.
// ---------------------------------------------------------------------------
__global__ void __launch_bounds__(256) knn_kernel(const float* __restrict__ pos, int n)
{
    __shared__ float cd2 [4][CAP];
    __shared__ int   cidx[4][CAP];
    __shared__ int   cnt[4];

    const int tid = threadIdx.x;
    const int i0  = blockIdx.x * 4;
    if (tid < 4) cnt[tid] = 0;
    __syncthreads();

    float qx[4], qy[4], qz[4], sqi[4];
    #pragma unroll
    for (int t = 0; t < 4; t++) {
        int i = i0 + t; if (i >= n) i = n - 1;
        qx[t] = pos[3 * i + 0];
        qy[t] = pos[3 * i + 1];
        qz[t] = pos[3 * i + 2];
        sqi[t] = qx[t] * qx[t] + qy[t] * qy[t] + qz[t] * qz[t];
    }

    for (int j = tid; j < n; j += 256) {
        const float px = pos[3 * j + 0];
        const float py = pos[3 * j + 1];
        const float pz = pos[3 * j + 2];
        const float sqj = px * px + py * py + pz * pz;
        #pragma unroll
        for (int t = 0; t < 4; t++) {
            const float dot = px * qx[t] + py * qy[t] + pz * qz[t];
            const float d2  = (sqi[t] + sqj) - 2.0f * dot;   // same formula as reference
            if (d2 <= R2) {
                int p = atomicAdd(&cnt[t], 1);
                if (p < CAP) { cd2[t][p] = d2; cidx[t][p] = j; }
            }
        }
    }
    __syncthreads();

    const int t = tid >> 6;        // target within block
    const int l = tid & 63;
    const int i = i0 + t;
    if (i >= n) return;

    int M = cnt[t]; if (M > CAP) M = CAP;

    if (M <= KNBR) {
        g_nbr[i * KNBR + l] = (l < M) ? cidx[t][l] : i;   // pad with self
    } else {
        for (int m = l; m < M; m += 64) {
            const float dm = cd2[t][m];
            const int   im = cidx[t][m];
            int rank = 0;
            for (int q = 0; q < M; q++) {
                const float dq = cd2[t][q];
                rank += (dq < dm) || (dq == dm && cidx[t][q] < im);
            }
            if (rank < KNBR) g_nbr[i * KNBR + rank] = cidx[t][m];
        }
    }
}

// ---------------------------------------------------------------------------
// G precompute: G = x @ W1[0:64,:] + b1   (per-source-point layer-1 part)
// ---------------------------------------------------------------------------
__global__ void __launch_bounds__(128) g_kernel(
    const float* __restrict__ x, const float* __restrict__ W1,
    const float* __restrict__ b1, int n)
{
    __shared__ __align__(16) float xs[8 * 64];
    const int tid = threadIdx.x;
    const int i0  = blockIdx.x * 8;

    for (int idx = tid; idx < 512; idx += 128) {
        int p = idx >> 6, d = idx & 63;
        xs[idx] = (i0 + p < n) ? x[(size_t)(i0 + p) * 64 + d] : 0.0f;
    }
    __syncthreads();

    const int p  = tid >> 4;
    const int c4 = (tid & 15) * 4;
    if (i0 + p >= n) return;

    float4 acc = *(const float4*)&b1[c4];
    const float* xr = &xs[p * 64];
    #pragma unroll 8
    for (int d = 0; d < 64; d++) {
        const float xv = xr[d];
        float4 w = *(const float4*)&W1[d * 64 + c4];
        acc.x = fmaf(xv, w.x, acc.x);
        acc.y = fmaf(xv, w.y, acc.y);
        acc.z = fmaf(xv, w.z, acc.z);
        acc.w = fmaf(xv, w.w, acc.w);
    }
    *(float4*)&g_G[(size_t)(i0 + p) * 64 + c4] = acc;
}

// ---------------------------------------------------------------------------
// Main edge kernel: one block per point, 128 threads.
// Phase A: h1[c][nk] = relu(G[j] + rel @ W1[64:67]) into shared [c][nk].
// Phase B: register tile 4 channels x 16 neighbors per thread (single pass,
//          32 packed f32x2 accumulators): per d-step only 4 LDS.128 (h,
//          broadcast) + 4 LDG.64 (w, coalesced) feed 32 FMA2 -> L1 and FMA
//          pipes balanced. Channels mapped {cg, cg+32, cg+64, cg+96} so the
//          weight LDGs are lane-consecutive.
// ---------------------------------------------------------------------------
__global__ void __launch_bounds__(128, 4) compute_kernel(
    const float* __restrict__ pos, const float* __restrict__ W1,
    const float* __restrict__ b2, int n)
{
    __shared__ __align__(16) float H1s[H1DIM * 68];   // [c][nk], stride 68
    __shared__ int   nbr_s[KNBR];
    __shared__ float relx[KNBR], rely[KNBR], relz[KNBR];
    __shared__ float red[4][H2DIM];                   // per-ngroup channel maxes

    const int i   = blockIdx.x;
    const int tid = threadIdx.x;
    if (i >= n) return;

    if (tid < KNBR) {
        const int j = g_nbr[i * KNBR + tid];
        nbr_s[tid] = j;
        relx[tid] = pos[3 * j + 0] - pos[3 * i + 0];
        rely[tid] = pos[3 * j + 1] - pos[3 * i + 1];
        relz[tid] = pos[3 * j + 2] - pos[3 * i + 2];
    }
    __syncthreads();

    // ---- Phase A ----
    {
        const int nk0 = tid & 7;
        const int c4  = (tid >> 3) * 4;
        const float4 wx = *(const float4*)&W1[64 * 64 + c4];
        const float4 wy = *(const float4*)&W1[65 * 64 + c4];
        const float4 wz = *(const float4*)&W1[66 * 64 + c4];
        #pragma unroll
        for (int it = 0; it < 8; it++) {
            const int nk = nk0 + it * 8;
            const int j  = nbr_s[nk];
            const float4 g4 = *(const float4*)&g_G[(size_t)j * 64 + c4];
            const float rx = relx[nk], ry = rely[nk], rz = relz[nk];
            float4 a;
            a.x = fmaf(rx, wx.x, fmaf(ry, wy.x, fmaf(rz, wz.x, g4.x)));
            a.y = fmaf(rx, wx.y, fmaf(ry, wy.y, fmaf(rz, wz.y, g4.y)));
            a.z = fmaf(rx, wx.z, fmaf(ry, wy.z, fmaf(rz, wz.z, g4.z)));
            a.w = fmaf(rx, wx.w, fmaf(ry, wy.w, fmaf(rz, wz.w, g4.w)));
            H1s[(c4 + 0) * 68 + nk] = fmaxf(a.x, 0.0f);
            H1s[(c4 + 1) * 68 + nk] = fmaxf(a.y, 0.0f);
            H1s[(c4 + 2) * 68 + nk] = fmaxf(a.z, 0.0f);
            H1s[(c4 + 3) * 68 + nk] = fmaxf(a.w, 0.0f);
        }
    }
    __syncthreads();

    // ---- Phase B: layer 2 + max-agg, 4ch x 16nbr register tile ----
    {
        const int cg = tid & 31;        // channel group lane (0..31)
        const int ng = tid >> 5;        // neighbor group (0..3) -> nbrs [16ng,16ng+16)
        const int nb = ng * 16;

        ull acc[4][8];
        #pragma unroll
        for (int k = 0; k < 4; k++)
            #pragma unroll
            for (int p = 0; p < 8; p++) acc[k][p] = 0ull;

        const ull*   wp = reinterpret_cast<const ull*>(g_W2d) + cg;  // + d*128
        const float* hr = &H1s[nb];

        #pragma unroll 4
        for (int d = 0; d < H1DIM; d++) {
            const ull w0 = wp[0];
            const ull w1 = wp[32];
            const ull w2 = wp[64];
            const ull w3 = wp[96];
            wp += H2DIM;
            #pragma unroll
            for (int p = 0; p < 4; p++) {
                const ulonglong2 hv = *reinterpret_cast<const ulonglong2*>(hr + 4 * p);
                fma2(acc[0][2 * p + 0], hv.x, w0);
                fma2(acc[0][2 * p + 1], hv.y, w0);
                fma2(acc[1][2 * p + 0], hv.x, w1);
                fma2(acc[1][2 * p + 1], hv.y, w1);
                fma2(acc[2][2 * p + 0], hv.x, w2);
                fma2(acc[2][2 * p + 1], hv.y, w2);
                fma2(acc[3][2 * p + 0], hv.x, w3);
                fma2(acc[3][2 * p + 1], hv.y, w3);
            }
            hr += 68;
        }

        // local max over this thread's 16 neighbors, per channel
        #pragma unroll
        for (int k = 0; k < 4; k++) {
            float m = -1e30f;
            #pragma unroll
            for (int p = 0; p < 8; p++) {
                const float lo = __uint_as_float((unsigned)(acc[k][p] & 0xffffffffu));
                const float hi = __uint_as_float((unsigned)(acc[k][p] >> 32));
                m = fmaxf(m, fmaxf(lo, hi));
            }
            red[ng][32 * k + cg] = m;
        }
    }
    __syncthreads();

    // cross-ngroup reduction; relu(max+b2) == max relu(z+b2) (max monotone)
    {
        const int c = tid;
        const float v = fmaxf(fmaxf(red[0][c], red[1][c]),
                              fmaxf(red[2][c], red[3][c]));
        g_AGG[(size_t)i * H2DIM + c] = fmaxf(v + b2[c], 0.0f);
    }
}

// ---------------------------------------------------------------------------
// Global layer GEMM: out = relu(AGG @ Wg + bg). 32-point tiles, 256 threads,
// packed f32x2 accumulation over rows, Wg duplicated pairs from g_Wgd.
// ---------------------------------------------------------------------------
__global__ void __launch_bounds__(256) gemm_kernel(
    const float* __restrict__ bg, float* __restrict__ out, int n)
{
    __shared__ __align__(16) float As[H2DIM * 36];   // [d][r], stride 36
    const int tid = threadIdx.x;
    const int i0  = blockIdx.x * 32;

    for (int idx = tid; idx < 32 * H2DIM; idx += 256) {
        const int r = idx >> 7, d = idx & 127;
        const int row = (i0 + r < n) ? (i0 + r) : (n - 1);
        As[d * 36 + r] = g_AGG[(size_t)row * H2DIM + d];
    }
    __syncthreads();

    const int c = tid;   // output channel 0..255
    ull acc[16];
    #pragma unroll
    for (int p = 0; p < 16; p++) acc[p] = 0ull;

    const ull* wp = reinterpret_cast<const ull*>(g_Wgd) + c;
    #pragma unroll 2
    for (int d = 0; d < H2DIM; d++) {
        const ull wd = *wp; wp += ODIM;
        const float* ar = &As[d * 36];
        #pragma unroll
        for (int p = 0; p < 8; p++) {
            const ulonglong2 av = *reinterpret_cast<const ulonglong2*>(ar + 4 * p);
            fma2(acc[2 * p + 0], av.x, wd);
            fma2(acc[2 * p + 1], av.y, wd);
        }
    }

    const float bc = bg[c];
    #pragma unroll
    for (int k = 0; k < 16; k++) {          // acc[k] -> rows (2k, 2k+1)
        const float lo = __uint_as_float((unsigned)(acc[k] & 0xffffffffu));
        const float hi = __uint_as_float((unsigned)(acc[k] >> 32));
        const int r0 = i0 + 2 * k, r1 = r0 + 1;
        if (r0 < n) out[(size_t)r0 * ODIM + c] = fmaxf(lo + bc, 0.0f);
        if (r1 < n) out[(size_t)r1 * ODIM + c] = fmaxf(hi + bc, 0.0f);
    }
}

// ---------------------------------------------------------------------------
extern "C" void kernel_launch(void* const* d_in, const int* in_sizes, int n_in,
                              void* d_out, int out_size)
{
    const float* x   = (const float*)d_in[0];
    const float* pos = (const float*)d_in[1];
    // d_in[2] = batch (all zeros, unused)
    const float* W1  = (const float*)d_in[3];
    const float* b1  = (const float*)d_in[4];
    const float* W2  = (const float*)d_in[5];
    const float* b2  = (const float*)d_in[6];
    const float* Wg  = (const float*)d_in[7];
    const float* bg  = (const float*)d_in[8];
    float* out = (float*)d_out;

    const int n = in_sizes[2];   // batch vector length == N

    prep_kernel<<<(H1DIM * H2DIM + H2DIM * ODIM + 255) / 256, 256>>>(W2, Wg);
    knn_kernel<<<(n + 3) / 4, 256>>>(pos, n);
    g_kernel<<<(n + 7) / 8, 128>>>(x, W1, b1, n);
    compute_kernel<<<n, 128>>>(pos, W1, b2, n);
    gemm_kernel<<<(n + 31) / 32, 256>>>(bg, out, n);
}